// round 2
// baseline (speedup 1.0000x reference)
#include <cuda_runtime.h>
#include <cuda_bf16.h>
#include <stdint.h>

#define BB 4
#define NN 2048
#define MM 8192
#define DD 128
#define SS 1024   // NUM_SEGMENTS

// ---------------- scratch (static __device__, no allocation) ----------------
__device__ float g_seg_sum[BB * SS * DD];  // 2 MB: per-(b,seg) sums
__device__ int   g_cnt[BB * SS];           // per-(b,seg) row counts
__device__ float g_inv[BB * SS];           // 1/(cnt + 1e-10)
__device__ int   g_off[BB * SS];           // exclusive prefix (within batch)
__device__ int   g_rows[BB * MM];          // row ids grouped by segment

// ---------------- 1) fused counting sort: one block per batch ----------------
// hist (shared atomics) -> scan (shared) -> scatter (shared cursors). No global atomics.
__global__ __launch_bounds__(1024) void k_sort(const int* __restrict__ idx_src) {
    __shared__ int sh_cnt[SS];
    __shared__ int sh_scan[SS];
    const int b = blockIdx.x;
    const int t = threadIdx.x;

    sh_cnt[t] = 0;
    __syncthreads();

    // each thread owns 8 source rows: 4t..4t+3 and 4096+4t..4096+4t+3
    const int4* p = (const int4*)(idx_src + b * MM);
    int4 a0 = p[t];
    int4 a1 = p[t + 1024];
    atomicAdd(&sh_cnt[a0.x], 1); atomicAdd(&sh_cnt[a0.y], 1);
    atomicAdd(&sh_cnt[a0.z], 1); atomicAdd(&sh_cnt[a0.w], 1);
    atomicAdd(&sh_cnt[a1.x], 1); atomicAdd(&sh_cnt[a1.y], 1);
    atomicAdd(&sh_cnt[a1.z], 1); atomicAdd(&sh_cnt[a1.w], 1);
    __syncthreads();

    // Hillis-Steele inclusive scan over 1024 counts
    int v = sh_cnt[t];
    sh_scan[t] = v;
    __syncthreads();
    #pragma unroll
    for (int d = 1; d < SS; d <<= 1) {
        int add = (t >= d) ? sh_scan[t - d] : 0;
        __syncthreads();
        sh_scan[t] += add;
        __syncthreads();
    }
    int excl = sh_scan[t] - v;
    g_cnt[b * SS + t] = v;
    g_inv[b * SS + t] = 1.0f / ((float)v + 1e-10f);
    g_off[b * SS + t] = excl;
    __syncthreads();

    // reuse sh_scan as fill cursors
    sh_scan[t] = excl;
    __syncthreads();

    int* rows = g_rows + b * MM;
    int base0 = 4 * t;
    int base1 = 4096 + 4 * t;
    int q;
    q = atomicAdd(&sh_scan[a0.x], 1); rows[q] = base0 + 0;
    q = atomicAdd(&sh_scan[a0.y], 1); rows[q] = base0 + 1;
    q = atomicAdd(&sh_scan[a0.z], 1); rows[q] = base0 + 2;
    q = atomicAdd(&sh_scan[a0.w], 1); rows[q] = base0 + 3;
    q = atomicAdd(&sh_scan[a1.x], 1); rows[q] = base1 + 0;
    q = atomicAdd(&sh_scan[a1.y], 1); rows[q] = base1 + 1;
    q = atomicAdd(&sh_scan[a1.z], 1); rows[q] = base1 + 2;
    q = atomicAdd(&sh_scan[a1.w], 1); rows[q] = base1 + 3;
}

// ---------------- 2) per-(b,segment) sum: one warp per segment, MLP=4 ----------------
__global__ void k_segsum(const float* __restrict__ src) {
    int warp = (blockIdx.x * blockDim.x + threadIdx.x) >> 5;  // 0..BB*SS-1
    int lane = threadIdx.x & 31;
    if (warp >= BB * SS) return;
    int b = warp >> 10;                 // warp / SS
    int cnt = g_cnt[warp];
    int off = g_off[warp];
    const int* rows = g_rows + b * MM + off;
    const float* base = src + (size_t)b * MM * DD;

    float4 acc0 = {0,0,0,0}, acc1 = {0,0,0,0}, acc2 = {0,0,0,0}, acc3 = {0,0,0,0};
    int r = 0;
    for (; r + 4 <= cnt; r += 4) {
        int m0 = rows[r], m1 = rows[r+1], m2 = rows[r+2], m3 = rows[r+3];
        float4 v0 = ((const float4*)(base + (size_t)m0 * DD))[lane];
        float4 v1 = ((const float4*)(base + (size_t)m1 * DD))[lane];
        float4 v2 = ((const float4*)(base + (size_t)m2 * DD))[lane];
        float4 v3 = ((const float4*)(base + (size_t)m3 * DD))[lane];
        acc0.x += v0.x; acc0.y += v0.y; acc0.z += v0.z; acc0.w += v0.w;
        acc1.x += v1.x; acc1.y += v1.y; acc1.z += v1.z; acc1.w += v1.w;
        acc2.x += v2.x; acc2.y += v2.y; acc2.z += v2.z; acc2.w += v2.w;
        acc3.x += v3.x; acc3.y += v3.y; acc3.z += v3.z; acc3.w += v3.w;
    }
    for (; r < cnt; r++) {
        int m = rows[r];
        float4 v = ((const float4*)(base + (size_t)m * DD))[lane];
        acc0.x += v.x; acc0.y += v.y; acc0.z += v.z; acc0.w += v.w;
    }
    acc0.x += acc1.x + acc2.x + acc3.x;
    acc0.y += acc1.y + acc2.y + acc3.y;
    acc0.z += acc1.z + acc2.z + acc3.z;
    acc0.w += acc1.w + acc2.w + acc3.w;
    ((float4*)(g_seg_sum + (size_t)warp * DD))[lane] = acc0;
}

// ---------------- 3) per-(b,target) gather * inv: one warp per target ----------------
__global__ void k_gather(const int* __restrict__ idx_tgt, float* __restrict__ out) {
    int warp = (blockIdx.x * blockDim.x + threadIdx.x) >> 5;  // 0..BB*NN-1
    int lane = threadIdx.x & 31;
    if (warp >= BB * NN) return;
    int b = warp >> 11;                 // warp / NN
    int s = idx_tgt[warp];
    int slot = (b << 10) + s;
    float inv = g_inv[slot];
    float4 v = ((const float4*)(g_seg_sum + (size_t)slot * DD))[lane];
    v.x *= inv; v.y *= inv; v.z *= inv; v.w *= inv;
    ((float4*)(out + (size_t)warp * DD))[lane] = v;
}

// ---------------- launch ----------------
extern "C" void kernel_launch(void* const* d_in, const int* in_sizes, int n_in,
                              void* d_out, int out_size) {
    const int*   idx_tgt = (const int*)d_in[0];    // [B, N, 1]
    const int*   idx_src = (const int*)d_in[1];    // [B, M, 1]
    const float* src     = (const float*)d_in[2];  // [B, M, D]
    float*       out     = (float*)d_out;          // [B, N, D]

    k_sort  <<<BB, 1024>>>(idx_src);
    k_segsum<<<(BB * SS * 32 + 255) / 256, 256>>>(src);
    k_gather<<<(BB * NN * 32 + 255) / 256, 256>>>(idx_tgt, out);
}

// round 3
// speedup vs baseline: 1.2709x; 1.2709x over previous
#include <cuda_runtime.h>
#include <cuda_bf16.h>
#include <stdint.h>

#define BB 4
#define NN 2048
#define MM 8192
#define DD 128
#define SS 1024   // NUM_SEGMENTS
#define HB 8      // hist blocks per batch
#define ROWS_PER_BLK (MM / HB)   // 1024

// ---------------- scratch (static __device__, no allocation) ----------------
__device__ float g_seg_sum[BB * SS * DD];   // 2 MB
__device__ int   g_blkhist[BB * HB * SS];   // per-(batch, block) histograms
__device__ int   g_cnt[BB * SS];
__device__ float g_inv[BB * SS];
__device__ int   g_off[BB * SS];
__device__ int   g_rows[BB * MM];

// ---------------- 1) per-block private histogram (no global atomics) ----------------
__global__ __launch_bounds__(256) void k_blockhist(const int* __restrict__ idx_src) {
    __shared__ int h[SS];
    const int b = blockIdx.x >> 3;
    const int i = blockIdx.x & 7;
    const int t = threadIdx.x;

    ((int4*)h)[t] = make_int4(0, 0, 0, 0);
    __syncthreads();

    int4 a = ((const int4*)(idx_src + b * MM + i * ROWS_PER_BLK))[t];
    atomicAdd(&h[a.x], 1); atomicAdd(&h[a.y], 1);
    atomicAdd(&h[a.z], 1); atomicAdd(&h[a.w], 1);
    __syncthreads();

    ((int4*)(g_blkhist + (b * HB + i) * SS))[t] = ((int4*)h)[t];
}

// ---------------- 2) scan + scatter (shared cursors, exact global offsets) ----------------
__global__ __launch_bounds__(256) void k_scatter(const int* __restrict__ idx_src) {
    __shared__ int curs[SS];      // per-segment fill cursor (global positions)
    __shared__ int wsum[8];       // per-warp totals for block scan
    const int b = blockIdx.x >> 3;
    const int i = blockIdx.x & 7;
    const int t = threadIdx.x;
    const int lane = t & 31;
    const int w = t >> 5;

    // thread t owns segments 4t..4t+3
    int4 tot = make_int4(0, 0, 0, 0);   // total count per owned segment
    int4 pre = make_int4(0, 0, 0, 0);   // count from blocks j < i
    #pragma unroll
    for (int j = 0; j < HB; j++) {
        int4 h4 = ((const int4*)(g_blkhist + (b * HB + j) * SS))[t];
        tot.x += h4.x; tot.y += h4.y; tot.z += h4.z; tot.w += h4.w;
        if (j < i) { pre.x += h4.x; pre.y += h4.y; pre.z += h4.z; pre.w += h4.w; }
    }

    // local inclusive prefixes within the 4 owned segments
    int l0 = tot.x, l1 = l0 + tot.y, l2 = l1 + tot.z, l3 = l2 + tot.w;  // l3 = thread total

    // warp-level inclusive scan of thread totals
    int inc = l3;
    #pragma unroll
    for (int d = 1; d < 32; d <<= 1) {
        int up = __shfl_up_sync(0xffffffffu, inc, d);
        if (lane >= d) inc += up;
    }
    if (lane == 31) wsum[w] = inc;
    __syncthreads();
    if (w == 0) {
        int v = (lane < 8) ? wsum[lane] : 0;
        #pragma unroll
        for (int d = 1; d < 8; d <<= 1) {
            int up = __shfl_up_sync(0xffffffffu, v, d);
            if (lane >= d) v += up;
        }
        if (lane < 8) wsum[lane] = v;   // inclusive warp-sum scan
    }
    __syncthreads();
    int excl = inc - l3 + (w > 0 ? wsum[w - 1] : 0);   // exclusive prefix of thread totals

    // global segment offsets (within batch) for owned segments
    int o0 = excl;
    int o1 = excl + l0;
    int o2 = excl + l1;
    int o3 = excl + l2;

    if (i == 0) {   // one block per batch publishes metadata for segsum/gather
        int s = 4 * t;
        g_cnt[b * SS + s + 0] = tot.x;  g_off[b * SS + s + 0] = o0;
        g_cnt[b * SS + s + 1] = tot.y;  g_off[b * SS + s + 1] = o1;
        g_cnt[b * SS + s + 2] = tot.z;  g_off[b * SS + s + 2] = o2;
        g_cnt[b * SS + s + 3] = tot.w;  g_off[b * SS + s + 3] = o3;
        g_inv[b * SS + s + 0] = 1.0f / ((float)tot.x + 1e-10f);
        g_inv[b * SS + s + 1] = 1.0f / ((float)tot.y + 1e-10f);
        g_inv[b * SS + s + 2] = 1.0f / ((float)tot.z + 1e-10f);
        g_inv[b * SS + s + 3] = 1.0f / ((float)tot.w + 1e-10f);
    }

    // cursors = global offset + contribution of earlier blocks
    curs[4 * t + 0] = o0 + pre.x;
    curs[4 * t + 1] = o1 + pre.y;
    curs[4 * t + 2] = o2 + pre.z;
    curs[4 * t + 3] = o3 + pre.w;
    __syncthreads();

    // scatter this block's 1024 rows via shared cursors
    int4 a = ((const int4*)(idx_src + b * MM + i * ROWS_PER_BLK))[t];
    int m = i * ROWS_PER_BLK + 4 * t;
    int* rows = g_rows + b * MM;
    int q;
    q = atomicAdd(&curs[a.x], 1); rows[q] = m + 0;
    q = atomicAdd(&curs[a.y], 1); rows[q] = m + 1;
    q = atomicAdd(&curs[a.z], 1); rows[q] = m + 2;
    q = atomicAdd(&curs[a.w], 1); rows[q] = m + 3;
}

// ---------------- 3) per-(b,segment) sum: one warp per segment, MLP=4 ----------------
__global__ void k_segsum(const float* __restrict__ src) {
    int warp = (blockIdx.x * blockDim.x + threadIdx.x) >> 5;
    int lane = threadIdx.x & 31;
    if (warp >= BB * SS) return;
    int b = warp >> 10;
    int cnt = g_cnt[warp];
    int off = g_off[warp];
    const int* rows = g_rows + b * MM + off;
    const float* base = src + (size_t)b * MM * DD;

    float4 acc0 = {0,0,0,0}, acc1 = {0,0,0,0}, acc2 = {0,0,0,0}, acc3 = {0,0,0,0};
    int r = 0;
    for (; r + 4 <= cnt; r += 4) {
        int m0 = rows[r], m1 = rows[r+1], m2 = rows[r+2], m3 = rows[r+3];
        float4 v0 = ((const float4*)(base + (size_t)m0 * DD))[lane];
        float4 v1 = ((const float4*)(base + (size_t)m1 * DD))[lane];
        float4 v2 = ((const float4*)(base + (size_t)m2 * DD))[lane];
        float4 v3 = ((const float4*)(base + (size_t)m3 * DD))[lane];
        acc0.x += v0.x; acc0.y += v0.y; acc0.z += v0.z; acc0.w += v0.w;
        acc1.x += v1.x; acc1.y += v1.y; acc1.z += v1.z; acc1.w += v1.w;
        acc2.x += v2.x; acc2.y += v2.y; acc2.z += v2.z; acc2.w += v2.w;
        acc3.x += v3.x; acc3.y += v3.y; acc3.z += v3.z; acc3.w += v3.w;
    }
    for (; r < cnt; r++) {
        int m = rows[r];
        float4 v = ((const float4*)(base + (size_t)m * DD))[lane];
        acc0.x += v.x; acc0.y += v.y; acc0.z += v.z; acc0.w += v.w;
    }
    acc0.x += acc1.x + acc2.x + acc3.x;
    acc0.y += acc1.y + acc2.y + acc3.y;
    acc0.z += acc1.z + acc2.z + acc3.z;
    acc0.w += acc1.w + acc2.w + acc3.w;
    ((float4*)(g_seg_sum + (size_t)warp * DD))[lane] = acc0;
}

// ---------------- 4) per-(b,target) gather * inv ----------------
__global__ void k_gather(const int* __restrict__ idx_tgt, float* __restrict__ out) {
    int warp = (blockIdx.x * blockDim.x + threadIdx.x) >> 5;
    int lane = threadIdx.x & 31;
    if (warp >= BB * NN) return;
    int b = warp >> 11;
    int s = idx_tgt[warp];
    int slot = (b << 10) + s;
    float inv = g_inv[slot];
    float4 v = ((const float4*)(g_seg_sum + (size_t)slot * DD))[lane];
    v.x *= inv; v.y *= inv; v.z *= inv; v.w *= inv;
    ((float4*)(out + (size_t)warp * DD))[lane] = v;
}

// ---------------- launch ----------------
extern "C" void kernel_launch(void* const* d_in, const int* in_sizes, int n_in,
                              void* d_out, int out_size) {
    const int*   idx_tgt = (const int*)d_in[0];
    const int*   idx_src = (const int*)d_in[1];
    const float* src     = (const float*)d_in[2];
    float*       out     = (float*)d_out;

    k_blockhist<<<BB * HB, 256>>>(idx_src);
    k_scatter  <<<BB * HB, 256>>>(idx_src);
    k_segsum   <<<(BB * SS * 32 + 255) / 256, 256>>>(src);
    k_gather   <<<(BB * NN * 32 + 255) / 256, 256>>>(idx_tgt, out);
}